// round 17
// baseline (speedup 1.0000x reference)
#include <cuda_runtime.h>
#include <cuda_bf16.h>
#include <math.h>
#include <stdint.h>

#define Bn 128
#define Tn 1024
#define Hn 512
#define BnHn (Bn * Hn)

union UF2 { unsigned long long u; float2 f; };

__device__ unsigned g_cnt[16 * 1024];   // [rg][t] CTA arrivals (target 8)

// bf16 two-term splits, packed once per launch.
__device__ __align__(16) __nv_bfloat16 g_Xhi[(size_t)Bn * Tn * Hn];
__device__ __align__(16) __nv_bfloat16 g_Xlo[(size_t)Bn * Tn * Hn];
__device__ __align__(16) __nv_bfloat16 g_Wth[Hn * Hn];   // Wx^T [n][k] hi
__device__ __align__(16) __nv_bfloat16 g_Wtl[Hn * Hn];   // Wx^T [n][k] lo
__device__ __align__(16) __nv_bfloat16 g_Whh[Hn * Hn];   // Wh^T [n][k] hi
__device__ __align__(16) __nv_bfloat16 g_Whl[Hn * Hn];   // Wh^T [n][k] lo

__global__ void zero_cnt() {
    int i = blockIdx.x * blockDim.x + threadIdx.x;
    if (i < 16 * 1024) g_cnt[i] = 0u;
}

__device__ __forceinline__ unsigned ld_acq(const unsigned* p) {
    unsigned v;
    asm volatile("ld.acquire.gpu.global.u32 %0, [%1];" : "=r"(v) : "l"(p));
    return v;
}

// ---- pack kernels ---------------------------------------------------------
__global__ __launch_bounds__(256) void pack_x(const float* __restrict__ X) {
    size_t i = ((size_t)blockIdx.x * 256 + threadIdx.x) * 4;
    float4 v = *(const float4*)(X + i);
    __nv_bfloat16 h0 = __float2bfloat16(v.x);
    __nv_bfloat16 h1 = __float2bfloat16(v.y);
    __nv_bfloat16 h2 = __float2bfloat16(v.z);
    __nv_bfloat16 h3 = __float2bfloat16(v.w);
    __nv_bfloat162 hp0(h0, h1), hp1(h2, h3);
    *(__nv_bfloat162*)(g_Xhi + i)     = hp0;
    *(__nv_bfloat162*)(g_Xhi + i + 2) = hp1;
    __nv_bfloat16 l0 = __float2bfloat16(v.x - __bfloat162float(h0));
    __nv_bfloat16 l1 = __float2bfloat16(v.y - __bfloat162float(h1));
    __nv_bfloat16 l2 = __float2bfloat16(v.z - __bfloat162float(h2));
    __nv_bfloat16 l3 = __float2bfloat16(v.w - __bfloat162float(h3));
    __nv_bfloat162 lp0(l0, l1), lp1(l2, l3);
    *(__nv_bfloat162*)(g_Xlo + i)     = lp0;
    *(__nv_bfloat162*)(g_Xlo + i + 2) = lp1;
}

__global__ __launch_bounds__(256) void pack_wt(const float* __restrict__ Wx) {
    int i = blockIdx.x * 256 + threadIdx.x;   // i = n*512 + k
    int n = i >> 9, k = i & 511;
    float v = Wx[(size_t)k * Hn + n];
    __nv_bfloat16 h = __float2bfloat16(v);
    g_Wth[i] = h;
    g_Wtl[i] = __float2bfloat16(v - __bfloat162float(h));
}

__global__ __launch_bounds__(256) void pack_wht(const float* __restrict__ Wh) {
    int i = blockIdx.x * 256 + threadIdx.x;   // i = n*512 + k
    int n = i >> 9, k = i & 511;
    float v = Wh[(size_t)k * Hn + n];
    __nv_bfloat16 h = __float2bfloat16(v);
    g_Whh[i] = h;
    g_Whl[i] = __float2bfloat16(v - __bfloat162float(h));
}

// ---- HMMA / ldmatrix helpers ----------------------------------------------
#define MMA_BF16(d, a, b) \
    asm volatile("mma.sync.aligned.m16n8k16.row.col.f32.bf16.bf16.f32 " \
        "{%0,%1,%2,%3}, {%4,%5,%6,%7}, {%8,%9}, {%0,%1,%2,%3};" \
        : "+f"((d)[0]), "+f"((d)[1]), "+f"((d)[2]), "+f"((d)[3]) \
        : "r"((a)[0]), "r"((a)[1]), "r"((a)[2]), "r"((a)[3]), \
          "r"((b)[0]), "r"((b)[1]))

#define LDSM_X4(r, a) \
    asm volatile("ldmatrix.sync.aligned.m8n8.x4.shared.b16 {%0,%1,%2,%3}, [%4];" \
        : "=r"((r)[0]), "=r"((r)[1]), "=r"((r)[2]), "=r"((r)[3]) : "r"(a))
#define LDSM_X2(r, a) \
    asm volatile("ldmatrix.sync.aligned.m8n8.x2.shared.b16 {%0,%1}, [%2];" \
        : "=r"((r)[0]), "=r"((r)[1]) : "r"(a))

__device__ __forceinline__ void cp16(uint32_t s, const void* g) {
    asm volatile("cp.async.cg.shared.global [%0], [%1], 16;" :: "r"(s), "l"(g));
}
#define CP_COMMIT() asm volatile("cp.async.commit_group;" ::: "memory")
#define CP_WAIT(n)  asm volatile("cp.async.wait_group %0;" :: "n"(n) : "memory")

// ---------------------------------------------------------------------------
// Phase 1: pre = X @ Wx + bias via mma.sync bf16 3-term split (R16, proven).
// ---------------------------------------------------------------------------
#define KC 64
#define KPAD 72
#define ATILE (128 * KPAD)
#define STAGE_ELEMS (4 * ATILE)
#define GEMM_SMEM (2 * STAGE_ELEMS * 2)

__global__ __launch_bounds__(256) void gemm_tc(
    const float* __restrict__ bias,
    float* __restrict__ out)
{
    extern __shared__ __nv_bfloat16 sg[];
    const uint32_t sb = (uint32_t)__cvta_generic_to_shared(sg);
    const int tid  = threadIdx.x;
    const int wid  = tid >> 5;
    const int lane = tid & 31;
    const int bn0  = blockIdx.x * 128;
    const int bm0  = blockIdx.y * 128;
    const int wm   = wid & 3;
    const int wn   = wid >> 2;
    const int grp  = lane >> 2;
    const int tig  = lane & 3;

    const int s_row = tid >> 3;
    const int s_gc  = tid & 7;

    float acc[2][8][4];
#pragma unroll
    for (int mt = 0; mt < 2; mt++)
#pragma unroll
        for (int nt = 0; nt < 8; nt++)
#pragma unroll
            for (int j = 0; j < 4; j++) acc[mt][nt][j] = 0.0f;

#define STAGEC(c, buf)                                                         \
    do {                                                                       \
        const int k0s = (c) * KC;                                              \
        const uint32_t dbase = sb + (uint32_t)(buf) * (STAGE_ELEMS * 2);       \
        _Pragma("unroll")                                                      \
        for (int i = 0; i < 4; i++) {                                          \
            int row = s_row + (i << 5);                                        \
            uint32_t doff = (uint32_t)(row * 144 + s_gc * 16);                 \
            size_t axoff = (size_t)(bm0 + row) * Hn + k0s + s_gc * 8;          \
            size_t bxoff = (size_t)(bn0 + row) * Hn + k0s + s_gc * 8;          \
            cp16(dbase + doff,             g_Xhi + axoff);                     \
            cp16(dbase + ATILE * 2 + doff, g_Xlo + axoff);                     \
            cp16(dbase + ATILE * 4 + doff, g_Wth + bxoff);                     \
            cp16(dbase + ATILE * 6 + doff, g_Wtl + bxoff);                     \
        }                                                                      \
        CP_COMMIT();                                                           \
    } while (0)

    STAGEC(0, 0);

    for (int c = 0; c < 8; c++) {
        if (c < 7) STAGEC(c + 1, (c + 1) & 1);
        if (c < 7) { CP_WAIT(1); } else { CP_WAIT(0); }
        __syncthreads();

        const __nv_bfloat16* Sb = sg + (c & 1) * STAGE_ELEMS;
        const __nv_bfloat16* Ah = Sb;
        const __nv_bfloat16* Al = Sb + ATILE;
        const __nv_bfloat16* Bh = Sb + 2 * ATILE;
        const __nv_bfloat16* Bl = Sb + 3 * ATILE;

#pragma unroll
        for (int ks = 0; ks < 4; ks++) {
            const int kk = ks * 16 + 2 * tig;
            uint32_t ah[2][4], al[2][4], bh[8][2], bl[8][2];
#pragma unroll
            for (int mt = 0; mt < 2; mt++) {
                int base = (wm * 32 + mt * 16 + grp) * KPAD + kk;
                ah[mt][0] = *(const uint32_t*)(Ah + base);
                ah[mt][1] = *(const uint32_t*)(Ah + base + 8 * KPAD);
                ah[mt][2] = *(const uint32_t*)(Ah + base + 8);
                ah[mt][3] = *(const uint32_t*)(Ah + base + 8 * KPAD + 8);
                al[mt][0] = *(const uint32_t*)(Al + base);
                al[mt][1] = *(const uint32_t*)(Al + base + 8 * KPAD);
                al[mt][2] = *(const uint32_t*)(Al + base + 8);
                al[mt][3] = *(const uint32_t*)(Al + base + 8 * KPAD + 8);
            }
#pragma unroll
            for (int nt = 0; nt < 8; nt++) {
                int nb = (wn * 64 + nt * 8 + grp) * KPAD + kk;
                bh[nt][0] = *(const uint32_t*)(Bh + nb);
                bh[nt][1] = *(const uint32_t*)(Bh + nb + 8);
                bl[nt][0] = *(const uint32_t*)(Bl + nb);
                bl[nt][1] = *(const uint32_t*)(Bl + nb + 8);
            }
#pragma unroll
            for (int mt = 0; mt < 2; mt++)
#pragma unroll
                for (int nt = 0; nt < 8; nt++) {
                    MMA_BF16(acc[mt][nt], ah[mt], bh[nt]);
                    MMA_BF16(acc[mt][nt], ah[mt], bl[nt]);
                    MMA_BF16(acc[mt][nt], al[mt], bh[nt]);
                }
        }
        __syncthreads();
    }

#pragma unroll
    for (int mt = 0; mt < 2; mt++) {
        const int m0 = bm0 + wm * 32 + mt * 16 + grp;
#pragma unroll
        for (int h = 0; h < 2; h++) {
            const int m  = m0 + 8 * h;
            const int gb = m >> 10;
            const int tt = m & 1023;
            float* dst = out + ((size_t)tt * Bn + gb) * Hn;
#pragma unroll
            for (int nt = 0; nt < 8; nt++) {
                const int cb = bn0 + wn * 64 + nt * 8 + 2 * tig;
                float2 v;
                v.x = acc[mt][nt][2 * h + 0] + bias[cb];
                v.y = acc[mt][nt][2 * h + 1] + bias[cb + 1];
                *(float2*)(dst + cb) = v;
            }
        }
    }
}

// ---------------------------------------------------------------------------
// Phase 2: persistent HMMA recurrence.
// 64 CTAs = 8 rowgroups (16 batch rows) x 8 colgroups (64 cols), 256 threads.
// Warp w -> n8 tile cols [c0+8w, c0+8w+8), full K=512, 4-product bf16 split.
// Wh^T slice (hi/lo) resident in smem, stride 520 (conflict-free ldmatrix).
// State converted to bf16 hi/lo in smem each step. Sync = proven L2 counter
// (8 producers per rowgroup).
// ---------------------------------------------------------------------------
#define SST 520                           // smem row stride (bf16)
#define WH_ELEMS (64 * SST)               // 33280 per split
#define S_ELEMS  (16 * SST)               // 8320 per split
#define RNN_SMEM ((2 * WH_ELEMS + 2 * S_ELEMS) * 2)   // 166400 bytes

__global__ __launch_bounds__(256) void rnn_tc(
    const float* __restrict__ state0,  // [B, H]
    float* __restrict__ out)           // [T, B, H] (holds pre on entry)
{
    extern __shared__ __nv_bfloat16 sr[];
    __nv_bfloat16* Whh = sr;                       // [64][SST]
    __nv_bfloat16* Whl = sr + WH_ELEMS;            // [64][SST]
    __nv_bfloat16* Shi = sr + 2 * WH_ELEMS;        // [16][SST]
    __nv_bfloat16* Slo = Shi + S_ELEMS;            // [16][SST]

    const int tid  = threadIdx.x;
    const int w    = tid >> 5;            // warp 0..7 -> n8 tile
    const int lane = tid & 31;
    const int cg   = blockIdx.x & 7;
    const int rg   = blockIdx.x >> 3;     // 0..7
    const int c0   = cg * 64;
    const int r0   = rg * 16;

    // ---- one-time: Wh^T slice (rows c0..c0+63 of [n][k]) -> smem, padded ----
    {
        const uint4* srcH = (const uint4*)(g_Whh + (size_t)c0 * Hn);
        const uint4* srcL = (const uint4*)(g_Whl + (size_t)c0 * Hn);
        for (int i = tid; i < 64 * 64; i += 256) {     // 64 rows x 64 uint4
            int n = i >> 6, g = i & 63;
            *(uint4*)(Whh + n * SST + g * 8) = srcH[n * 64 + g];
            *(uint4*)(Whl + n * SST + g * 8) = srcL[n * 64 + g];
        }
    }

    // ---- ldmatrix lane-address setup ----
    const int quad = lane >> 3;
    const int r8   = lane & 7;
    const int arow = (quad & 1) * 8 + r8;          // A tile order m0k0,m8k0,m0k8,m8k8
    const int akof = (quad >> 1) * 8;
    const uint32_t shi_b = (uint32_t)__cvta_generic_to_shared(Shi);
    uint32_t aHi = shi_b + (uint32_t)(arow * SST + akof) * 2;
    uint32_t aLo = aHi + S_ELEMS * 2;
    const uint32_t whh_b = (uint32_t)__cvta_generic_to_shared(Whh);
    const int bk = ((lane >> 3) & 1) * 8;          // B tile order k0, k8
    uint32_t bHi = whh_b + (uint32_t)((w * 8 + r8) * SST + bk) * 2;
    uint32_t bLo = bHi + WH_ELEMS * 2;

    // ---- epilogue mapping: rows {grp, grp+8}, cols {cE, cE+1} ----
    const int grp = lane >> 2;
    const int tig = lane & 3;
    const int cE  = c0 + w * 8 + 2 * tig;
    float* op0 = out + (size_t)(r0 + grp) * Hn + cE;
    float* op1 = out + (size_t)(r0 + grp + 8) * Hn + cE;

    unsigned* cnt = &g_cnt[rg * 1024];

    __syncthreads();                      // Wh smem ready

    for (int t = 0; t < Tn; t++) {
        const size_t toff = (size_t)t * BnHn;
        float2 pre0 = __ldcg((const float2*)(op0 + toff));
        float2 pre1 = __ldcg((const float2*)(op1 + toff));

        if (t > 0) {
            while (ld_acq(&cnt[t - 1]) < 8u) { }
        }

        // ---- stage state rows [r0, r0+16) -> bf16 hi/lo smem ----
        const float* prev = (t == 0) ? state0 : (out + toff - BnHn);
#pragma unroll
        for (int i = 0; i < 8; i++) {
            int idx = tid + (i << 8);          // 0..2047 (float4 units)
            int row = idx >> 7;                // 0..15
            int k4  = (idx & 127) << 2;        // 0..508
            float4 v = __ldcg((const float4*)(prev + (size_t)(r0 + row) * Hn + k4));
            __nv_bfloat16 h0 = __float2bfloat16(v.x);
            __nv_bfloat16 h1 = __float2bfloat16(v.y);
            __nv_bfloat16 h2 = __float2bfloat16(v.z);
            __nv_bfloat16 h3 = __float2bfloat16(v.w);
            __nv_bfloat162 hp0(h0, h1), hp1(h2, h3);
            __nv_bfloat16 l0 = __float2bfloat16(v.x - __bfloat162float(h0));
            __nv_bfloat16 l1 = __float2bfloat16(v.y - __bfloat162float(h1));
            __nv_bfloat16 l2 = __float2bfloat16(v.z - __bfloat162float(h2));
            __nv_bfloat16 l3 = __float2bfloat16(v.w - __bfloat162float(h3));
            __nv_bfloat162 lp0(l0, l1), lp1(l2, l3);
            __nv_bfloat16* dh = Shi + row * SST + k4;
            __nv_bfloat16* dl = Slo + row * SST + k4;
            *(__nv_bfloat162*)(dh)     = hp0;
            *(__nv_bfloat162*)(dh + 2) = hp1;
            *(__nv_bfloat162*)(dl)     = lp0;
            *(__nv_bfloat162*)(dl + 2) = lp1;
        }
        __syncthreads();

        // ---- MMA: 32 k-steps, 4 independent product chains ----
        float ahh[4] = {0, 0, 0, 0}, ahl[4] = {0, 0, 0, 0};
        float alh[4] = {0, 0, 0, 0}, all4[4] = {0, 0, 0, 0};
#pragma unroll
        for (int ks = 0; ks < 32; ks++) {
            const uint32_t ko = (uint32_t)(ks * 32);   // 16 bf16 per k-step
            uint32_t fah[4], fal[4], fbh[2], fbl[2];
            LDSM_X4(fah, aHi + ko);
            LDSM_X4(fal, aLo + ko);
            LDSM_X2(fbh, bHi + ko);
            LDSM_X2(fbl, bLo + ko);
            MMA_BF16(ahh, fah, fbh);
            MMA_BF16(ahl, fah, fbl);
            MMA_BF16(alh, fal, fbh);
            MMA_BF16(all4, fal, fbl);
        }

        // ---- epilogue: combine, tanh, publish ----
        {
            float s0 = (ahh[0] + all4[0]) + (ahl[0] + alh[0]);
            float s1 = (ahh[1] + all4[1]) + (ahl[1] + alh[1]);
            float s2 = (ahh[2] + all4[2]) + (ahl[2] + alh[2]);
            float s3 = (ahh[3] + all4[3]) + (ahl[3] + alh[3]);
            float2 v0, v1;
            v0.x = tanhf(pre0.x + s0);
            v0.y = tanhf(pre0.y + s1);
            v1.x = tanhf(pre1.x + s2);
            v1.y = tanhf(pre1.y + s3);
            __stcg((float2*)(op0 + toff), v0);
            __stcg((float2*)(op1 + toff), v1);
        }
        __syncthreads();                  // stores issued + Shi/Slo reads done

        if (t != Tn - 1 && tid == 0) {
            __threadfence();
            atomicAdd(&cnt[t], 1u);
        }
    }
}

extern "C" void kernel_launch(void* const* d_in, const int* in_sizes, int n_in,
                              void* d_out, int out_size)
{
    const float* X    = (const float*)d_in[0];  // inputs_tensor [B,T,H]
    const float* S0   = (const float*)d_in[1];  // state_tensor  [1,B,H]
    const float* Wx   = (const float*)d_in[2];  // [H,H]
    const float* Wh   = (const float*)d_in[3];  // [H,H]
    const float* bias = (const float*)d_in[4];  // [H]
    float* out = (float*)d_out;                 // [T,B,H]

    (void)in_sizes; (void)n_in; (void)out_size;

    cudaFuncSetAttribute(gemm_tc,
                         cudaFuncAttributeMaxDynamicSharedMemorySize,
                         GEMM_SMEM);
    cudaFuncSetAttribute(rnn_tc,
                         cudaFuncAttributeMaxDynamicSharedMemorySize,
                         RNN_SMEM);

    zero_cnt<<<32, 512>>>();
    pack_x<<<65536, 256>>>(X);
    pack_wt<<<1024, 256>>>(Wx);
    pack_wht<<<1024, 256>>>(Wh);

    dim3 g1(Hn / 128, (Bn * Tn) / 128);  // (4, 1024)
    gemm_tc<<<g1, 256, GEMM_SMEM>>>(bias, out);

    rnn_tc<<<64, 256, RNN_SMEM>>>(S0, out);
}